// round 10
// baseline (speedup 1.0000x reference)
#include <cuda_runtime.h>

// Problem-fixed maxima (scratch must be static __device__ arrays — no allocs allowed)
#define NMAX 100000
#define EMAX 1600000
#define HDIM 64
#define GMAX 64

__device__ int   g_is64;                         // 1 if index inputs are int64, 0 if int32
__device__ int   g_cnt_in[NMAX];                 // in-degree (excl self-loop)
__device__ int   g_off[NMAX];                    // CSR row offsets (by dst)
__device__ int   g_cur[NMAX];                    // placement cursors
__device__ float g_dinv[NMAX];                   // deg^-1/2 (incl self-loop)
__device__ int   g_src[EMAX];                    // edge src (int32)
__device__ int   g_dst[EMAX];                    // edge dst (int32)
__device__ int   g_csr_src[EMAX];                // CSR column (src) indices
__device__ float g_tmp[(size_t)NMAX * HDIM];     // dinv[r] * (X @ W)[r]  (pre-scaled!)
__device__ float g_h[(size_t)NMAX * HDIM];       // aggregated activations
__device__ float g_pool[GMAX * HDIM];
__device__ float g_cntf[GMAX];

// ---------------------------------------------------------------------------
// Detect int64 vs int32 edge_index (odd 32-bit words all zero => int64).
__global__ void k_detect(const unsigned int* __restrict__ w) {
    int nz = 0;
    for (int i = threadIdx.x; i < 2048; i += blockDim.x)
        if (w[2 * i + 1] != 0u) nz = 1;
    nz = __syncthreads_or(nz);
    if (threadIdx.x == 0) g_is64 = nz ? 0 : 1;
}

__global__ void k_init(int n, int g) {
    int i = blockIdx.x * blockDim.x + threadIdx.x;
    if (i < n) g_cnt_in[i] = 0;
    if (i < g * HDIM) g_pool[i] = 0.0f;
    if (i < g) g_cntf[i] = 0.0f;
}

// edge indices -> int32 arrays + in-degree histogram on dst (dtype-flexible)
__global__ void k_edge_prep(const void* __restrict__ ei, int E, int n) {
    int e = blockIdx.x * blockDim.x + threadIdx.x;
    if (e >= E) return;
    int s, d;
    if (g_is64) {
        const long long* p = (const long long*)ei;
        s = (int)p[e];
        d = (int)p[(size_t)E + e];
    } else {
        const int* p = (const int*)ei;
        s = p[e];
        d = p[(size_t)E + e];
    }
    if ((unsigned)s >= (unsigned)n) s = 0;   // defensive clamp (should never hit)
    if ((unsigned)d >= (unsigned)n) d = 0;
    g_src[e] = s;
    g_dst[e] = d;
    atomicAdd(&g_cnt_in[d], 1);
}

// Single-block exclusive scan over n counts -> offsets, cursors, dinv (fused)
__global__ void k_scan(int n) {
    __shared__ int ssum[1024];
    int tid = threadIdx.x;
    int chunk = (n + 1023) >> 10;
    int start = min(tid * chunk, n);
    int end = min(start + chunk, n);
    int s = 0;
    for (int i = start; i < end; i++) s += g_cnt_in[i];
    ssum[tid] = s;
    __syncthreads();
    for (int off = 1; off < 1024; off <<= 1) {
        int v = (tid >= off) ? ssum[tid - off] : 0;
        __syncthreads();
        ssum[tid] += v;
        __syncthreads();
    }
    int run = (tid > 0) ? ssum[tid - 1] : 0;
    for (int i = start; i < end; i++) {
        int c = g_cnt_in[i];
        g_off[i] = run;
        g_cur[i] = run;
        g_dinv[i] = rsqrtf((float)(c + 1));   // +1 self-loop, always > 0
        run += c;
    }
}

__global__ void k_place(int E) {
    int e = blockIdx.x * blockDim.x + threadIdx.x;
    if (e >= E) return;
    int pos = atomicAdd(&g_cur[g_dst[e]], 1);
    if ((unsigned)pos < (unsigned)EMAX) g_csr_src[pos] = g_src[e];
}

// ---------------------------------------------------------------------------
// g_tmp[r,64] = dinv[r] * (X[r,K] @ W[K,64])   (layer 1)
// Block: 256 threads = 64 rows x 4 col-groups of 16. K chunks of 64.
__global__ void __launch_bounds__(256) k_gemm1(const float* __restrict__ X,
                                               const float* __restrict__ W,
                                               int n, int K) {
    __shared__ float xs[64][65];
    __shared__ float ws[64][64];
    int tid = threadIdx.x;
    int row0 = blockIdx.x * 64;
    int r = tid & 63;
    int cg = tid >> 6;
    float acc[16];
#pragma unroll
    for (int j = 0; j < 16; j++) acc[j] = 0.0f;

    for (int k0 = 0; k0 < K; k0 += 64) {
        for (int i = tid; i < 64 * 64; i += 256) {
            int kr = i >> 6, cc = i & 63;
            ws[kr][cc] = W[(size_t)(k0 + kr) * HDIM + cc];
        }
        for (int i = tid; i < 64 * 64; i += 256) {
            int rr = i >> 6, cc = i & 63;
            int gr = row0 + rr;
            xs[rr][cc] = (gr < n) ? X[(size_t)gr * K + k0 + cc] : 0.0f;
        }
        __syncthreads();
#pragma unroll
        for (int k = 0; k < 64; k++) {
            float xv = xs[r][k];
#pragma unroll
            for (int j = 0; j < 16; j++) acc[j] += xv * ws[k][cg * 16 + j];
        }
        __syncthreads();
    }
    int gr = row0 + r;
    if (gr < n) {
        float di = g_dinv[gr];
#pragma unroll
        for (int j = 0; j < 16; j++)
            g_tmp[(size_t)gr * HDIM + cg * 16 + j] = di * acc[j];
    }
}

// g_tmp[r,64] = dinv[r] * (relu(g_h)[r,64] @ W[64,64])   (layer 2)
__global__ void __launch_bounds__(256) k_gemm2(const float* __restrict__ W, int n) {
    __shared__ float xs[64][65];
    __shared__ float ws[64][64];
    int tid = threadIdx.x;
    int row0 = blockIdx.x * 64;
    int r = tid & 63;
    int cg = tid >> 6;
    float acc[16];
#pragma unroll
    for (int j = 0; j < 16; j++) acc[j] = 0.0f;

    for (int i = tid; i < 64 * 64; i += 256) {
        int kr = i >> 6, cc = i & 63;
        ws[kr][cc] = W[(size_t)kr * HDIM + cc];
    }
    for (int i = tid; i < 64 * 64; i += 256) {
        int rr = i >> 6, cc = i & 63;
        int gr = row0 + rr;
        xs[rr][cc] = (gr < n) ? fmaxf(g_h[(size_t)gr * HDIM + cc], 0.0f) : 0.0f;
    }
    __syncthreads();
#pragma unroll
    for (int k = 0; k < 64; k++) {
        float xv = xs[r][k];
#pragma unroll
        for (int j = 0; j < 16; j++) acc[j] += xv * ws[k][cg * 16 + j];
    }
    int gr = row0 + r;
    if (gr < n) {
        float di = g_dinv[gr];
#pragma unroll
        for (int j = 0; j < 16; j++)
            g_tmp[(size_t)gr * HDIM + cg * 16 + j] = di * acc[j];
    }
}

// ---------------------------------------------------------------------------
// g_h[d,:] = dinv[d] * ( sum_{s in CSR(d)} tmp'[s,:] + tmp'[d,:] ) + b
// tmp' is pre-scaled by dinv. 16 threads/node, float4 each, edge loop x4 unroll.
__global__ void __launch_bounds__(256) k_agg(const float* __restrict__ bias, int n) {
    int t = blockIdx.x * blockDim.x + threadIdx.x;
    int node = t >> 4;
    int q = t & 15;
    if (node >= n) return;
    const float4* tmp4 = (const float4*)g_tmp;
    int off = g_off[node];
    int cnt = g_cnt_in[node];
    float ax = 0.0f, ay = 0.0f, az = 0.0f, aw = 0.0f;
    int i = 0;
    for (; i + 4 <= cnt; i += 4) {
        int s0 = g_csr_src[off + i + 0];
        int s1 = g_csr_src[off + i + 1];
        int s2 = g_csr_src[off + i + 2];
        int s3 = g_csr_src[off + i + 3];
        float4 v0 = tmp4[(size_t)s0 * 16 + q];
        float4 v1 = tmp4[(size_t)s1 * 16 + q];
        float4 v2 = tmp4[(size_t)s2 * 16 + q];
        float4 v3 = tmp4[(size_t)s3 * 16 + q];
        ax += (v0.x + v1.x) + (v2.x + v3.x);
        ay += (v0.y + v1.y) + (v2.y + v3.y);
        az += (v0.z + v1.z) + (v2.z + v3.z);
        aw += (v0.w + v1.w) + (v2.w + v3.w);
    }
    for (; i < cnt; i++) {
        int s = g_csr_src[off + i];
        float4 v = tmp4[(size_t)s * 16 + q];
        ax += v.x; ay += v.y; az += v.z; aw += v.w;
    }
    float di = g_dinv[node];
    float4 sv = tmp4[(size_t)node * 16 + q];          // self term (already dinv-scaled)
    float4 b = ((const float4*)bias)[q];
    float4 o;
    o.x = di * (ax + sv.x) + b.x;
    o.y = di * (ay + sv.y) + b.y;
    o.z = di * (az + sv.z) + b.z;
    o.w = di * (aw + sv.w) + b.w;
    ((float4*)g_h)[(size_t)node * 16 + q] = o;
}

// ---------------------------------------------------------------------------
// relu(h2) -> logits (warp dot with Wa) + graph pooling atomics
__global__ void __launch_bounds__(256) k_final(const void* __restrict__ batch,
                                               const float* __restrict__ Wa,
                                               const float* __restrict__ ba,
                                               float* __restrict__ out, int n, int g) {
    int warp = (blockIdx.x * blockDim.x + threadIdx.x) >> 5;
    int lane = threadIdx.x & 31;
    if (warp >= n) return;
    float v0 = fmaxf(g_h[(size_t)warp * HDIM + lane], 0.0f);
    float v1 = fmaxf(g_h[(size_t)warp * HDIM + 32 + lane], 0.0f);
    float p = v0 * Wa[lane] + v1 * Wa[lane + 32];
#pragma unroll
    for (int o = 16; o > 0; o >>= 1) p += __shfl_xor_sync(0xffffffffu, p, o);
    int b = g_is64 ? (int)((const long long*)batch)[warp]
                   : ((const int*)batch)[warp];
    if ((unsigned)b >= (unsigned)g) b = 0;   // defensive clamp
    atomicAdd(&g_pool[b * HDIM + lane], v0);
    atomicAdd(&g_pool[b * HDIM + 32 + lane], v1);
    if (lane == 0) {
        out[warp] = p + ba[0];
        atomicAdd(&g_cntf[b], 1.0f);
    }
}

__global__ void k_value(const float* __restrict__ Wc, const float* __restrict__ bc,
                        float* __restrict__ out, int n, int g) {
    int i = threadIdx.x;
    if (i >= g) return;
    float c = fmaxf(g_cntf[i], 1.0f);
    float s = 0.0f;
#pragma unroll
    for (int j = 0; j < HDIM; j++) s += g_pool[i * HDIM + j] * Wc[j];
    out[n + i] = s / c + bc[0];
}

// ---------------------------------------------------------------------------
extern "C" void kernel_launch(void* const* d_in, const int* in_sizes, int n_in,
                              void* d_out, int out_size) {
    const float* x     = (const float*)d_in[0];
    const void*  ei    = d_in[1];
    const void*  batch = d_in[2];
    const float* W1    = (const float*)d_in[3];
    const float* b1    = (const float*)d_in[4];
    const float* W2    = (const float*)d_in[5];
    const float* b2    = (const float*)d_in[6];
    const float* Wa    = (const float*)d_in[7];
    const float* ba    = (const float*)d_in[8];
    const float* Wc    = (const float*)d_in[9];
    const float* bc    = (const float*)d_in[10];

    int N = in_sizes[2];          // batch vector length = #nodes
    int E = in_sizes[1] / 2;      // edge_index is (2, E)
    int F = in_sizes[0] / N;      // 128
    int G = out_size - N;         // graphs

    float* out = (float*)d_out;

    const int T = 256;
    int nb_n = (N + T - 1) / T;
    int nb_e = (E + T - 1) / T;
    int nb_a = (N * 16 + T - 1) / T;
    int nb_g = (N + 63) / 64;
    int nb_f = (N * 32 + T - 1) / T;

    // dtype probe + CSR build (+dinv fused into scan)
    k_detect<<<1, 256>>>((const unsigned int*)ei);
    k_init<<<nb_n, T>>>(N, G);
    k_edge_prep<<<nb_e, T>>>(ei, E, N);
    k_scan<<<1, 1024>>>(N);
    k_place<<<nb_e, T>>>(E);

    // Layer 1
    k_gemm1<<<nb_g, 256>>>(x, W1, N, F);
    k_agg<<<nb_a, T>>>(b1, N);

    // Layer 2
    k_gemm2<<<nb_g, 256>>>(W2, N);
    k_agg<<<nb_a, T>>>(b2, N);

    // Epilogue
    k_final<<<nb_f, T>>>(batch, Wa, ba, out, N, G);
    k_value<<<1, 64>>>(Wc, bc, out, N, G);
}

// round 11
// speedup vs baseline: 1.4987x; 1.4987x over previous
#include <cuda_runtime.h>

// Problem-fixed maxima (scratch must be static __device__ arrays — no allocs allowed)
#define NMAX 100000
#define EMAX 1600000
#define HDIM 64
#define GMAX 64
#define SCAN_B 256                               // counts per scan block
#define NBLK ((NMAX + SCAN_B - 1) / SCAN_B)      // 391

__device__ int   g_is64;                         // 1 if index inputs are int64, 0 if int32
__device__ int   g_cnt_in[NMAX];                 // in-degree (excl self-loop)
__device__ int   g_off[NMAX];                    // CSR row offsets (by dst)
__device__ int   g_cur[NMAX];                    // placement cursors
__device__ float g_dinv[NMAX];                   // deg^-1/2 (incl self-loop)
__device__ int   g_src[EMAX];                    // edge src (int32)
__device__ int   g_dst[EMAX];                    // edge dst (int32)
__device__ int   g_csr_src[EMAX];                // CSR column (src) indices
__device__ int   g_bsum[1024];                   // per-block count sums
__device__ int   g_bpre[1024];                   // exclusive prefix of block sums
__device__ float g_tmp[(size_t)NMAX * HDIM];     // dinv[r] * (X @ W)[r]  (pre-scaled)
__device__ float g_h[(size_t)NMAX * HDIM];       // aggregated activations
__device__ float g_pool[GMAX * HDIM];
__device__ float g_cntf[GMAX];

// ---------------------------------------------------------------------------
// Detect int64 vs int32 edge_index (odd 32-bit words all zero => int64).
__global__ void k_detect(const unsigned int* __restrict__ w) {
    int nz = 0;
    for (int i = threadIdx.x; i < 2048; i += blockDim.x)
        if (w[2 * i + 1] != 0u) nz = 1;
    nz = __syncthreads_or(nz);
    if (threadIdx.x == 0) g_is64 = nz ? 0 : 1;
}

__global__ void k_init(int n, int g) {
    int i = blockIdx.x * blockDim.x + threadIdx.x;
    if (i < n) g_cnt_in[i] = 0;
    if (i < g * HDIM) g_pool[i] = 0.0f;
    if (i < g) g_cntf[i] = 0.0f;
}

// edge indices -> int32 arrays + in-degree histogram on dst (dtype-flexible)
__global__ void k_edge_prep(const void* __restrict__ ei, int E, int n) {
    int e = blockIdx.x * blockDim.x + threadIdx.x;
    if (e >= E) return;
    int s, d;
    if (g_is64) {
        const long long* p = (const long long*)ei;
        s = (int)p[e];
        d = (int)p[(size_t)E + e];
    } else {
        const int* p = (const int*)ei;
        s = p[e];
        d = p[(size_t)E + e];
    }
    if ((unsigned)s >= (unsigned)n) s = 0;   // defensive clamp (should never hit)
    if ((unsigned)d >= (unsigned)n) d = 0;
    g_src[e] = s;
    g_dst[e] = d;
    atomicAdd(&g_cnt_in[d], 1);
}

// ---------------------------------------------------------------------------
// Phase 1: per-block sums of 256 counts
__global__ void __launch_bounds__(SCAN_B) k_bsum(int n) {
    __shared__ int sd[SCAN_B];
    int i = blockIdx.x * SCAN_B + threadIdx.x;
    int v = (i < n) ? g_cnt_in[i] : 0;
    sd[threadIdx.x] = v;
    __syncthreads();
#pragma unroll
    for (int o = SCAN_B / 2; o > 0; o >>= 1) {
        if (threadIdx.x < o) sd[threadIdx.x] += sd[threadIdx.x + o];
        __syncthreads();
    }
    if (threadIdx.x == 0) g_bsum[blockIdx.x] = sd[0];
}

// Phase 2: single block scans the (<=1024) block sums -> exclusive prefixes
__global__ void __launch_bounds__(1024) k_scan_bsum(int nb) {
    __shared__ int s[1024];
    int tid = threadIdx.x;
    s[tid] = (tid < nb) ? g_bsum[tid] : 0;
    __syncthreads();
    for (int off = 1; off < 1024; off <<= 1) {
        int v = (tid >= off) ? s[tid - off] : 0;
        __syncthreads();
        s[tid] += v;
        __syncthreads();
    }
    if (tid < nb) g_bpre[tid] = s[tid] - g_bsum[tid];   // exclusive
}

// Phase 3: per-block local exclusive scan + block prefix; write off/cur/dinv
__global__ void __launch_bounds__(SCAN_B) k_offsets(int n) {
    __shared__ int s[SCAN_B];
    int tid = threadIdx.x;
    int i = blockIdx.x * SCAN_B + tid;
    int c = (i < n) ? g_cnt_in[i] : 0;
    s[tid] = c;
    __syncthreads();
#pragma unroll
    for (int off = 1; off < SCAN_B; off <<= 1) {
        int v = (tid >= off) ? s[tid - off] : 0;
        __syncthreads();
        s[tid] += v;
        __syncthreads();
    }
    if (i < n) {
        int pre = g_bpre[blockIdx.x] + s[tid] - c;   // exclusive prefix
        g_off[i] = pre;
        g_cur[i] = pre;
        g_dinv[i] = rsqrtf((float)(c + 1));          // +1 self-loop, always > 0
    }
}

__global__ void k_place(int E) {
    int e = blockIdx.x * blockDim.x + threadIdx.x;
    if (e >= E) return;
    int pos = atomicAdd(&g_cur[g_dst[e]], 1);
    if ((unsigned)pos < (unsigned)EMAX) g_csr_src[pos] = g_src[e];
}

// ---------------------------------------------------------------------------
// g_tmp[r,64] = dinv[r] * (X[r,K] @ W[K,64])   (layer 1)
__global__ void __launch_bounds__(256) k_gemm1(const float* __restrict__ X,
                                               const float* __restrict__ W,
                                               int n, int K) {
    __shared__ float xs[64][65];
    __shared__ float ws[64][64];
    int tid = threadIdx.x;
    int row0 = blockIdx.x * 64;
    int r = tid & 63;
    int cg = tid >> 6;
    float acc[16];
#pragma unroll
    for (int j = 0; j < 16; j++) acc[j] = 0.0f;

    for (int k0 = 0; k0 < K; k0 += 64) {
        for (int i = tid; i < 64 * 64; i += 256) {
            int kr = i >> 6, cc = i & 63;
            ws[kr][cc] = W[(size_t)(k0 + kr) * HDIM + cc];
        }
        for (int i = tid; i < 64 * 64; i += 256) {
            int rr = i >> 6, cc = i & 63;
            int gr = row0 + rr;
            xs[rr][cc] = (gr < n) ? X[(size_t)gr * K + k0 + cc] : 0.0f;
        }
        __syncthreads();
#pragma unroll
        for (int k = 0; k < 64; k++) {
            float xv = xs[r][k];
#pragma unroll
            for (int j = 0; j < 16; j++) acc[j] += xv * ws[k][cg * 16 + j];
        }
        __syncthreads();
    }
    int gr = row0 + r;
    if (gr < n) {
        float di = g_dinv[gr];
#pragma unroll
        for (int j = 0; j < 16; j++)
            g_tmp[(size_t)gr * HDIM + cg * 16 + j] = di * acc[j];
    }
}

// g_tmp[r,64] = dinv[r] * (relu(g_h)[r,64] @ W[64,64])   (layer 2)
__global__ void __launch_bounds__(256) k_gemm2(const float* __restrict__ W, int n) {
    __shared__ float xs[64][65];
    __shared__ float ws[64][64];
    int tid = threadIdx.x;
    int row0 = blockIdx.x * 64;
    int r = tid & 63;
    int cg = tid >> 6;
    float acc[16];
#pragma unroll
    for (int j = 0; j < 16; j++) acc[j] = 0.0f;

    for (int i = tid; i < 64 * 64; i += 256) {
        int kr = i >> 6, cc = i & 63;
        ws[kr][cc] = W[(size_t)kr * HDIM + cc];
    }
    for (int i = tid; i < 64 * 64; i += 256) {
        int rr = i >> 6, cc = i & 63;
        int gr = row0 + rr;
        xs[rr][cc] = (gr < n) ? fmaxf(g_h[(size_t)gr * HDIM + cc], 0.0f) : 0.0f;
    }
    __syncthreads();
#pragma unroll
    for (int k = 0; k < 64; k++) {
        float xv = xs[r][k];
#pragma unroll
        for (int j = 0; j < 16; j++) acc[j] += xv * ws[k][cg * 16 + j];
    }
    int gr = row0 + r;
    if (gr < n) {
        float di = g_dinv[gr];
#pragma unroll
        for (int j = 0; j < 16; j++)
            g_tmp[(size_t)gr * HDIM + cg * 16 + j] = di * acc[j];
    }
}

// ---------------------------------------------------------------------------
// g_h[d,:] = dinv[d] * ( sum_{s in CSR(d)} tmp'[s,:] + tmp'[d,:] ) + b
// tmp' pre-scaled by dinv. 16 threads/node, float4 each, edge loop x4 unroll.
__global__ void __launch_bounds__(256) k_agg(const float* __restrict__ bias, int n) {
    int t = blockIdx.x * blockDim.x + threadIdx.x;
    int node = t >> 4;
    int q = t & 15;
    if (node >= n) return;
    const float4* tmp4 = (const float4*)g_tmp;
    int off = g_off[node];
    int cnt = g_cnt_in[node];
    float ax = 0.0f, ay = 0.0f, az = 0.0f, aw = 0.0f;
    int i = 0;
    for (; i + 4 <= cnt; i += 4) {
        int s0 = g_csr_src[off + i + 0];
        int s1 = g_csr_src[off + i + 1];
        int s2 = g_csr_src[off + i + 2];
        int s3 = g_csr_src[off + i + 3];
        float4 v0 = tmp4[(size_t)s0 * 16 + q];
        float4 v1 = tmp4[(size_t)s1 * 16 + q];
        float4 v2 = tmp4[(size_t)s2 * 16 + q];
        float4 v3 = tmp4[(size_t)s3 * 16 + q];
        ax += (v0.x + v1.x) + (v2.x + v3.x);
        ay += (v0.y + v1.y) + (v2.y + v3.y);
        az += (v0.z + v1.z) + (v2.z + v3.z);
        aw += (v0.w + v1.w) + (v2.w + v3.w);
    }
    for (; i < cnt; i++) {
        int s = g_csr_src[off + i];
        float4 v = tmp4[(size_t)s * 16 + q];
        ax += v.x; ay += v.y; az += v.z; aw += v.w;
    }
    float di = g_dinv[node];
    float4 sv = tmp4[(size_t)node * 16 + q];          // self term (already dinv-scaled)
    float4 b = ((const float4*)bias)[q];
    float4 o;
    o.x = di * (ax + sv.x) + b.x;
    o.y = di * (ay + sv.y) + b.y;
    o.z = di * (az + sv.z) + b.z;
    o.w = di * (aw + sv.w) + b.w;
    ((float4*)g_h)[(size_t)node * 16 + q] = o;
}

// ---------------------------------------------------------------------------
// relu(h2) -> logits (warp dot with Wa) + graph pooling atomics
__global__ void __launch_bounds__(256) k_final(const void* __restrict__ batch,
                                               const float* __restrict__ Wa,
                                               const float* __restrict__ ba,
                                               float* __restrict__ out, int n, int g) {
    int warp = (blockIdx.x * blockDim.x + threadIdx.x) >> 5;
    int lane = threadIdx.x & 31;
    if (warp >= n) return;
    float v0 = fmaxf(g_h[(size_t)warp * HDIM + lane], 0.0f);
    float v1 = fmaxf(g_h[(size_t)warp * HDIM + 32 + lane], 0.0f);
    float p = v0 * Wa[lane] + v1 * Wa[lane + 32];
#pragma unroll
    for (int o = 16; o > 0; o >>= 1) p += __shfl_xor_sync(0xffffffffu, p, o);
    int b = g_is64 ? (int)((const long long*)batch)[warp]
                   : ((const int*)batch)[warp];
    if ((unsigned)b >= (unsigned)g) b = 0;   // defensive clamp
    atomicAdd(&g_pool[b * HDIM + lane], v0);
    atomicAdd(&g_pool[b * HDIM + 32 + lane], v1);
    if (lane == 0) {
        out[warp] = p + ba[0];
        atomicAdd(&g_cntf[b], 1.0f);
    }
}

__global__ void k_value(const float* __restrict__ Wc, const float* __restrict__ bc,
                        float* __restrict__ out, int n, int g) {
    int i = threadIdx.x;
    if (i >= g) return;
    float c = fmaxf(g_cntf[i], 1.0f);
    float s = 0.0f;
#pragma unroll
    for (int j = 0; j < HDIM; j++) s += g_pool[i * HDIM + j] * Wc[j];
    out[n + i] = s / c + bc[0];
}

// ---------------------------------------------------------------------------
extern "C" void kernel_launch(void* const* d_in, const int* in_sizes, int n_in,
                              void* d_out, int out_size) {
    const float* x     = (const float*)d_in[0];
    const void*  ei    = d_in[1];
    const void*  batch = d_in[2];
    const float* W1    = (const float*)d_in[3];
    const float* b1    = (const float*)d_in[4];
    const float* W2    = (const float*)d_in[5];
    const float* b2    = (const float*)d_in[6];
    const float* Wa    = (const float*)d_in[7];
    const float* ba    = (const float*)d_in[8];
    const float* Wc    = (const float*)d_in[9];
    const float* bc    = (const float*)d_in[10];

    int N = in_sizes[2];          // batch vector length = #nodes
    int E = in_sizes[1] / 2;      // edge_index is (2, E)
    int F = in_sizes[0] / N;      // 128
    int G = out_size - N;         // graphs

    float* out = (float*)d_out;

    const int T = 256;
    int nb_n = (N + T - 1) / T;
    int nb_e = (E + T - 1) / T;
    int nb_a = (N * 16 + T - 1) / T;
    int nb_g = (N + 63) / 64;
    int nb_f = (N * 32 + T - 1) / T;
    int nb_s = (N + SCAN_B - 1) / SCAN_B;

    // dtype probe + CSR build (parallel 3-phase scan)
    k_detect<<<1, 256>>>((const unsigned int*)ei);
    k_init<<<nb_n, T>>>(N, G);
    k_edge_prep<<<nb_e, T>>>(ei, E, N);
    k_bsum<<<nb_s, SCAN_B>>>(N);
    k_scan_bsum<<<1, 1024>>>(nb_s);
    k_offsets<<<nb_s, SCAN_B>>>(N);
    k_place<<<nb_e, T>>>(E);

    // Layer 1
    k_gemm1<<<nb_g, 256>>>(x, W1, N, F);
    k_agg<<<nb_a, T>>>(b1, N);

    // Layer 2
    k_gemm2<<<nb_g, 256>>>(W2, N);
    k_agg<<<nb_a, T>>>(b2, N);

    // Epilogue
    k_final<<<nb_f, T>>>(batch, Wa, ba, out, N, G);
    k_value<<<1, 64>>>(Wc, bc, out, N, G);
}